// round 12
// baseline (speedup 1.0000x reference)
#include <cuda_runtime.h>
#include <cstdint>

#define B_    128
#define T_    128
#define N_    128
#define M_    256
#define FourM 1024
#define RANKS 8
#define MB    8

__device__ float g_XWx[(size_t)B_ * T_ * FourM];   // [b*T + t][j] : x@Wx + b
__device__ float g_UXt[(size_t)B_ * T_ * N_];      // [b][u][n]    : U(X^T) + bU

__device__ __forceinline__ float sigmoid_(float x) {
    return __fdividef(1.f, 1.f + __expf(-x));
}
__device__ __forceinline__ float tanh_(float x) {          // accurate (gates)
    float e = __expf(2.f * x);
    return 1.f - __fdividef(2.f, e + 1.f);
}
__device__ __forceinline__ float tanha_(float x) {         // fast (attention)
    float y;
    asm("tanh.approx.f32 %0, %1;" : "=f"(y) : "f"(x));
    return y;
}
__device__ __forceinline__ uint32_t smem_u32(const void* p) {
    return (uint32_t)__cvta_generic_to_shared(p);
}
__device__ __forceinline__ uint32_t mapa_rank(uint32_t a, uint32_t r) {
    uint32_t d;
    asm("mapa.shared::cluster.u32 %0, %1, %2;" : "=r"(d) : "r"(a), "r"(r));
    return d;
}
__device__ __forceinline__ void st_cluster4(uint32_t a, float4 v) {
    asm volatile("st.shared::cluster.v4.f32 [%0], {%1,%2,%3,%4};"
                 :: "r"(a), "f"(v.x), "f"(v.y), "f"(v.z), "f"(v.w) : "memory");
}
__device__ __forceinline__ void st_cluster2(uint32_t a, float x, float y) {
    asm volatile("st.shared::cluster.v2.f32 [%0], {%1,%2};"
                 :: "r"(a), "f"(x), "f"(y) : "memory");
}
__device__ __forceinline__ void cl_arrive_() {
    asm volatile("barrier.cluster.arrive.aligned;" ::: "memory");
}
__device__ __forceinline__ void cl_wait_() {
    asm volatile("barrier.cluster.wait.aligned;" ::: "memory");
}
#define FMAX2(d, a, b, c) \
    asm("fma.rn.f32x2 %0, %1, %2, %3;" : "=l"(d) : "l"(a), "l"(b), "l"(c))

// ---------------------------------------------------------------------------
// Kernel 1: g_XWx = X @ Wx + b
// ---------------------------------------------------------------------------
__global__ void __launch_bounds__(256) xwx_gemm(const float* __restrict__ X,
                                                const float* __restrict__ Wx,
                                                const float* __restrict__ bias) {
    __shared__ float As[16][64];
    __shared__ float Bs[16][64];
    const int tid  = threadIdx.x;
    const int row0 = blockIdx.y * 64;
    const int col0 = blockIdx.x * 64;
    const int tx = tid & 15;
    const int ty = tid >> 4;
    const int am = tid >> 2;
    const int ak = (tid & 3) * 4;
    const int bk = tid >> 4;
    const int bj = (tid & 15) * 4;

    float acc[4][4];
#pragma unroll
    for (int i = 0; i < 4; i++)
#pragma unroll
        for (int j = 0; j < 4; j++) acc[i][j] = 0.f;

    for (int k0 = 0; k0 < 128; k0 += 16) {
        float4 av = *(const float4*)(X + (row0 + am) * 128 + k0 + ak);
        As[ak + 0][am] = av.x;
        As[ak + 1][am] = av.y;
        As[ak + 2][am] = av.z;
        As[ak + 3][am] = av.w;
        *(float4*)&Bs[bk][bj] = *(const float4*)(Wx + (k0 + bk) * FourM + col0 + bj);
        __syncthreads();
#pragma unroll
        for (int k = 0; k < 16; k++) {
            float4 a4 = *(const float4*)&As[k][ty * 4];
            float4 b4 = *(const float4*)&Bs[k][tx * 4];
            float a[4] = {a4.x, a4.y, a4.z, a4.w};
            float b[4] = {b4.x, b4.y, b4.z, b4.w};
#pragma unroll
            for (int i = 0; i < 4; i++)
#pragma unroll
                for (int j = 0; j < 4; j++) acc[i][j] = fmaf(a[i], b[j], acc[i][j]);
        }
        __syncthreads();
    }
    float4 b4 = *(const float4*)(bias + col0 + tx * 4);
    float bb[4] = {b4.x, b4.y, b4.z, b4.w};
#pragma unroll
    for (int i = 0; i < 4; i++) {
        float4 rr = make_float4(acc[i][0] + bb[0], acc[i][1] + bb[1],
                                acc[i][2] + bb[2], acc[i][3] + bb[3]);
        *(float4*)&g_XWx[(size_t)(row0 + ty * 4 + i) * FourM + col0 + tx * 4] = rr;
    }
}

// ---------------------------------------------------------------------------
// Kernel 2: g_UXt[b][u][n] = sum_t X[b][t][n]*Ud[t][u] + bU[u]
// ---------------------------------------------------------------------------
__global__ void __launch_bounds__(256) uxt_kernel(const float* __restrict__ X,
                                                  const float* __restrict__ Ud,
                                                  const float* __restrict__ bU) {
    __shared__ float Xs[32][128];
    __shared__ float Us[32][128];
    const int b   = blockIdx.x;
    const int tid = threadIdx.x;
    const int n   = tid & 127;
    const int uh  = tid >> 7;

    float acc[64];
#pragma unroll
    for (int i = 0; i < 64; ++i) acc[i] = 0.f;

    for (int t0 = 0; t0 < 128; t0 += 32) {
        for (int l = tid; l < 32 * 128; l += 256) {
            int tt = l >> 7, nn = l & 127;
            Xs[tt][nn] = X[(b * 128 + t0 + tt) * 128 + nn];
            Us[tt][nn] = Ud[(t0 + tt) * 128 + nn];
        }
        __syncthreads();
#pragma unroll 2
        for (int tt = 0; tt < 32; ++tt) {
            float xv = Xs[tt][n];
            const float* up = &Us[tt][uh * 64];
#pragma unroll
            for (int uu = 0; uu < 64; ++uu) acc[uu] = fmaf(xv, up[uu], acc[uu]);
        }
        __syncthreads();
    }
#pragma unroll 4
    for (int uu = 0; uu < 64; ++uu) {
        int u = uh * 64 + uu;
        g_UXt[(size_t)(b * 128 + u) * 128 + n] = acc[uu] + bU[u];
    }
}

// ---------------------------------------------------------------------------
// Kernel 3: pipelined cluster kernel.
//   A:  p1 GEMM (Wh regs, f32x2) interleaved with p3 attention of step t-1
//   B:  gates (+fused z-reduce) || single-warp softmax(t-1)+output
//   C:  h broadcast + Wd partials + DSMEM push
//   split cluster barriers (arrive early, wait late) — no CCTL L1 flush
// ---------------------------------------------------------------------------
struct SM {
    float h_dup[8][512];        // h duplicated: [b][2m]=[b][2m+1]=h[m]
    float zbuf[8][8][64][2];    // p1 partials [q][b][colpair][elem]
    float hs_own[8][68];        // [b][0:32)=h slice,[32:64)=c (padded)
    float c_loc[8][32];
    float wloc[16][8][128];     // p2 partials [kq][b][u]
    float wrecv[8][128];
    float wsm[128];
    float epart[16][128];
    float vds[128];
    float bWs[128];
};

__global__ void __launch_bounds__(512, 1) __cluster_dims__(RANKS, 1, 1)
darnn_main(const float* __restrict__ X, const float* __restrict__ h0,
           const float* __restrict__ s0, const float* __restrict__ Wh,
           const float* __restrict__ Wd, const float* __restrict__ bW,
           const float* __restrict__ vd, float* __restrict__ out) {
    extern __shared__ char smraw[];
    SM& s = *reinterpret_cast<SM*>(smraw);
    const int tid = threadIdx.x;
    const int r   = blockIdx.x & 7;
    const int b0  = (blockIdx.x >> 3) * MB;
    const int gb  = b0 + r;

    // ---- persistent register weights ----
    const int q   = tid >> 6;               // p1 k-range (32 rows)
    const int cg  = tid & 63;               // p1 col pair
    const int gC  = (cg >> 4) * 256 + r * 32 + ((cg * 2) & 31);
    unsigned long long Wp[32];
#pragma unroll
    for (int kk = 0; kk < 32; ++kk) {
        float2 w2 = *(const float2*)(Wh + (size_t)(q * 32 + kk) * FourM + gC);
        asm("mov.b64 %0, {%1, %2};" : "=l"(Wp[kk]) : "f"(w2.x), "f"(w2.y));
    }
    const int p2_uq = tid & 31;
    const int p2_kq = tid >> 5;             // 0..15
    float4 Wq[4];
#pragma unroll
    for (int i = 0; i < 4; ++i) {
        int kl = p2_kq * 4 + i;
        int gk = (kl < 32) ? (r * 32 + kl) : (256 + r * 32 + (kl - 32));
        Wq[i] = *(const float4*)(Wd + (size_t)gk * T_ + p2_uq * 4);
    }

    // ---- prologue: state + vectors ----
    for (int fid = tid; fid < 8 * 256; fid += 512) {
        int b = fid >> 8, m = fid & 255;
        float v = h0[(size_t)(b0 + b) * M_ + m];
        s.h_dup[b][2 * m]     = v;
        s.h_dup[b][2 * m + 1] = v;
    }
    if (tid < 256) {
        int b = tid >> 5, mi = tid & 31;
        s.c_loc[b][mi] = s0[(size_t)(b0 + b) * M_ + r * 32 + mi];
    }
    if (tid < 128) {
        s.vds[tid] = vd[tid];
        s.bWs[tid] = bW[tid];
        s.wsm[tid] = 0.f;       // benign value for the discarded t=0 p3 pass
    }

    // mappings
    const int g_b  = tid >> 5;              // gates batch (tid<256)
    const int g_mi = tid & 31;              // gates state index
    const int h_bb = tid >> 4;              // broadcast b (tid<128)
    const int h_qm = tid & 15;
    const int x_b  = tid >> 6;              // wloc-reduce batch
    const int x_j2 = tid & 63;              // wloc-reduce u pair
    const int e_uq = tid >> 5;              // p3 u-range (8 u's)
    const int e_ng = tid & 31;              // p3 n quad
    const int lane = tid - 480;             // softmax warp (tid>=480)

    // xw prefetch (gates threads): cols r*32+mi + {0,256,512,768} of step 0
    float xw0 = 0, xw1 = 0, xw2v = 0, xw3 = 0;
    const float* xwbase = g_XWx + ((size_t)(b0 + g_b) * T_) * FourM + r * 32 + g_mi;
    if (tid < 256) {
        xw0 = xwbase[0];
        xw1 = xwbase[256];
        xw2v = xwbase[512];
        xw3 = xwbase[768];
    }
    __syncthreads();

    const float* uxp = g_UXt + ((size_t)gb * T_ + e_uq * 8) * N_ + e_ng * 4;

    for (int t = 0; t < T_; ++t) {
        // ================= A: p1(t) interleaved with p3(t-1) ================
        {
            const float* hd = s.h_dup[0] + q * 64;
            float4 xnext = *(const float4*)uxp;
            float a0 = 0, a1 = 0, a2 = 0, a3 = 0;
#pragma unroll 1
            for (int b = 0; b < 8; ++b) {
                unsigned long long acc = 0ULL;
#pragma unroll
                for (int kk = 0; kk < 32; kk += 2) {
                    ulonglong2 hh = *(const ulonglong2*)(hd + b * 512 + 2 * kk);
                    FMAX2(acc, Wp[kk], hh.x, acc);
                    FMAX2(acc, Wp[kk + 1], hh.y, acc);
                }
                float z0, z1;
                asm("mov.b64 {%0, %1}, %2;" : "=f"(z0), "=f"(z1) : "l"(acc));
                *(float2*)&s.zbuf[q][b][cg][0] = make_float2(z0, z1);
                // p3 chunk (step t-1); discarded at t==0
                float4 xc = xnext;
                if (b < 7) xnext = *(const float4*)(uxp + (size_t)(b + 1) * N_);
                float wv = s.wsm[e_uq * 8 + b];
                float vv = s.vds[e_uq * 8 + b];
                a0 = fmaf(tanha_(wv + xc.x), vv, a0);
                a1 = fmaf(tanha_(wv + xc.y), vv, a1);
                a2 = fmaf(tanha_(wv + xc.z), vv, a2);
                a3 = fmaf(tanha_(wv + xc.w), vv, a3);
            }
            *(float4*)&s.epart[e_uq][e_ng * 4] = make_float4(a0, a1, a2, a3);
        }
        cl_arrive_();            // #1: this CTA done reading h_dup
        __syncthreads();

        // ================= B: gates (fused z-reduce) || softmax ============
        if (tid < 256) {
            float zi = xw0, zf = xw1, zg = xw2v, zo = xw3;
#pragma unroll
            for (int qq = 0; qq < 8; ++qq) {
                zi += s.zbuf[qq][g_b][g_mi >> 1][g_mi & 1];
                zf += s.zbuf[qq][g_b][16 + (g_mi >> 1)][g_mi & 1];
                zg += s.zbuf[qq][g_b][32 + (g_mi >> 1)][g_mi & 1];
                zo += s.zbuf[qq][g_b][48 + (g_mi >> 1)][g_mi & 1];
            }
            float ig = sigmoid_(zi);
            float fg = sigmoid_(zf);
            float gg = tanh_(zg);
            float og = sigmoid_(zo);
            float c  = fmaf(fg, s.c_loc[g_b][g_mi], ig * gg);
            float h  = og * tanh_(c);
            s.c_loc[g_b][g_mi]       = c;
            s.hs_own[g_b][g_mi]      = h;
            s.hs_own[g_b][32 + g_mi] = c;
        } else if (tid >= 480 && t > 0) {
            // single-warp softmax for step t-1, 4 n per lane
            float e0 = 0, e1 = 0, e2 = 0, e3 = 0;
#pragma unroll
            for (int uq = 0; uq < 16; ++uq) {
                float4 ep = *(const float4*)&s.epart[uq][lane * 4];
                e0 += ep.x; e1 += ep.y; e2 += ep.z; e3 += ep.w;
            }
            float mx = fmaxf(fmaxf(e0, e1), fmaxf(e2, e3));
#pragma unroll
            for (int o = 16; o; o >>= 1)
                mx = fmaxf(mx, __shfl_xor_sync(0xffffffffu, mx, o));
            float p0 = __expf(e0 - mx), p1 = __expf(e1 - mx);
            float p2 = __expf(e2 - mx), p3 = __expf(e3 - mx);
            float sm = p0 + p1 + p2 + p3;
#pragma unroll
            for (int o = 16; o; o >>= 1)
                sm += __shfl_xor_sync(0xffffffffu, sm, o);
            float inv = __fdividef(1.f, sm);
            size_t idx = ((size_t)gb * T_ + (t - 1)) * N_ + lane * 4;
            float4 xv = *(const float4*)(X + idx);
            *(float4*)(out + idx) = make_float4(xv.x * p0 * inv, xv.y * p1 * inv,
                                                xv.z * p2 * inv, xv.w * p3 * inv);
        }
        __syncthreads();
        cl_wait_();              // #1 complete: safe to overwrite h_dup

        // ================= C: broadcast h + Wd partials + push =============
        if (tid < 128) {
            float hx = s.hs_own[h_bb][h_qm * 2];
            float hy = s.hs_own[h_bb][h_qm * 2 + 1];
            float4 d4 = make_float4(hx, hx, hy, hy);
            uint32_t la = smem_u32(&s.h_dup[h_bb][r * 64 + h_qm * 4]);
#pragma unroll
            for (int d = 0; d < 8; ++d) st_cluster4(mapa_rank(la, d), d4);
        }
        {
#pragma unroll 1
            for (int b = 0; b < 8; ++b) {
                float a0 = 0, a1 = 0, a2 = 0, a3 = 0;
#pragma unroll
                for (int i = 0; i < 4; ++i) {
                    float hv = s.hs_own[b][p2_kq * 4 + i];
                    a0 = fmaf(hv, Wq[i].x, a0);
                    a1 = fmaf(hv, Wq[i].y, a1);
                    a2 = fmaf(hv, Wq[i].z, a2);
                    a3 = fmaf(hv, Wq[i].w, a3);
                }
                *(float4*)&s.wloc[p2_kq][b][p2_uq * 4] = make_float4(a0, a1, a2, a3);
            }
        }
        __syncthreads();
        {
            float s0_ = 0, s1_ = 0;
#pragma unroll
            for (int kq = 0; kq < 16; ++kq) {
                float2 p = *(const float2*)&s.wloc[kq][x_b][x_j2 * 2];
                s0_ += p.x;
                s1_ += p.y;
            }
            uint32_t la = smem_u32(&s.wrecv[r][x_j2 * 2]);
            st_cluster2(mapa_rank(la, x_b), s0_, s1_);
        }
        cl_arrive_();            // #2
        if (tid < 256) {         // prefetch xw(t+1) under barrier latency
            const float* xb = xwbase + (size_t)((t + 1 < T_) ? t + 1 : t) * FourM;
            xw0 = xb[0];
            xw1 = xb[256];
            xw2v = xb[512];
            xw3 = xb[768];
        }
        cl_wait_();              // #2 complete: wrecv + h_dup delivered

        // ================= D: combine w ====================================
        if (tid < 128) {
            float wv = s.bWs[tid];
#pragma unroll
            for (int src = 0; src < 8; ++src) wv += s.wrecv[src][tid];
            s.wsm[tid] = wv;
        }
        __syncthreads();
    }

    // ================= epilogue: attention + softmax for step T-1 =========
    {
        float a0 = 0, a1 = 0, a2 = 0, a3 = 0;
#pragma unroll
        for (int uu = 0; uu < 8; ++uu) {
            float wv = s.wsm[e_uq * 8 + uu];
            float vv = s.vds[e_uq * 8 + uu];
            float4 x4 = *(const float4*)(uxp + (size_t)uu * N_);
            a0 = fmaf(tanha_(wv + x4.x), vv, a0);
            a1 = fmaf(tanha_(wv + x4.y), vv, a1);
            a2 = fmaf(tanha_(wv + x4.z), vv, a2);
            a3 = fmaf(tanha_(wv + x4.w), vv, a3);
        }
        *(float4*)&s.epart[e_uq][e_ng * 4] = make_float4(a0, a1, a2, a3);
    }
    __syncthreads();
    if (tid >= 480) {
        float e0 = 0, e1 = 0, e2 = 0, e3 = 0;
#pragma unroll
        for (int uq = 0; uq < 16; ++uq) {
            float4 ep = *(const float4*)&s.epart[uq][lane * 4];
            e0 += ep.x; e1 += ep.y; e2 += ep.z; e3 += ep.w;
        }
        float mx = fmaxf(fmaxf(e0, e1), fmaxf(e2, e3));
#pragma unroll
        for (int o = 16; o; o >>= 1)
            mx = fmaxf(mx, __shfl_xor_sync(0xffffffffu, mx, o));
        float p0 = __expf(e0 - mx), p1 = __expf(e1 - mx);
        float p2 = __expf(e2 - mx), p3 = __expf(e3 - mx);
        float sm = p0 + p1 + p2 + p3;
#pragma unroll
        for (int o = 16; o; o >>= 1)
            sm += __shfl_xor_sync(0xffffffffu, sm, o);
        float inv = __fdividef(1.f, sm);
        size_t idx = ((size_t)gb * T_ + (T_ - 1)) * N_ + lane * 4;
        float4 xv = *(const float4*)(X + idx);
        *(float4*)(out + idx) = make_float4(xv.x * p0 * inv, xv.y * p1 * inv,
                                            xv.z * p2 * inv, xv.w * p3 * inv);
    }
}

// ---------------------------------------------------------------------------
// Inputs: X, h0, s0, Wx, Wh, b, Wd, bW, Ud, bU, vd, bv (bv cancels in softmax)
// ---------------------------------------------------------------------------
extern "C" void kernel_launch(void* const* d_in, const int* in_sizes, int n_in,
                              void* d_out, int out_size) {
    const float* X  = (const float*)d_in[0];
    const float* h0 = (const float*)d_in[1];
    const float* s0 = (const float*)d_in[2];
    const float* Wx = (const float*)d_in[3];
    const float* Wh = (const float*)d_in[4];
    const float* bz = (const float*)d_in[5];
    const float* Wd = (const float*)d_in[6];
    const float* bW = (const float*)d_in[7];
    const float* Ud = (const float*)d_in[8];
    const float* bU = (const float*)d_in[9];
    const float* vd = (const float*)d_in[10];
    float* out = (float*)d_out;

    cudaFuncSetAttribute(darnn_main, cudaFuncAttributeMaxDynamicSharedMemorySize,
                         (int)sizeof(SM));

    dim3 g1(FourM / 64, (B_ * T_) / 64);
    xwx_gemm<<<g1, 256>>>(X, Wx, bz);
    uxt_kernel<<<B_, 256>>>(X, Ud, bU);
    darnn_main<<<B_, 512, sizeof(SM)>>>(X, h0, s0, Wh, Wd, bW, vd, out);
}